// round 16
// baseline (speedup 1.0000x reference)
#include <cuda_runtime.h>

// GCN 2-layer, GB300 — round 16: pass reverted to R14-proven form (float2
// smem atomics are illegal — global-only on this part; R15 faulted). Round
// spent on k_scatter (61.7us vs ~25us IO floor): 512 threads x 4 edges,
// 4-replica rank counters (quarter the ATOMS contention), parallel replica
// merge. deg/pass/node kernels byte-identical to the 224.0us kernel.

#define NN     200000
#define NE     12800000
#define BSHIFT 11
#define BINW   2048
#define NBINS  98                    // ceil(NN / BINW)
#define NPAD   (NBINS * BINW)        // 200704
#define TILE   2048
#define NTILES (NE / TILE)           // 6250
#define CAPB   140000                // per-bin capacity; CAPB%4==0
#define CAPB4  (CAPB / 4)
#define NCHUNK 6                     // 98*6=588 blocks
#define NTP    512                   // threads for deg/pass blocks
#define NTS    512                   // threads for scatter blocks

__device__ unsigned d_edges[NBINS * CAPB];  // packed (localdst<<18)|src
__device__ int      d_cur[NBINS];           // per-bin cursors (zeroed by nodeC)
__device__ int      d_cnt[NPAD];            // degrees     (zeroed by nodeA)
__device__ float2   d_u  [NPAD];            // accumulators (zeroed by nodeB/C)
__device__ float    d_dinv[NN];
__device__ float2   d_g  [NN];
__device__ float2   d_h2 [NN];

// ---------------- partition: 512 thr, 4 edges/thr, 4-replica ranks --------

__global__ void k_scatter(const int4* __restrict__ src4,
                          const int4* __restrict__ dst4) {
    __shared__ unsigned stage[TILE];             // 8 KB
    __shared__ unsigned char binof[TILE];        // 2 KB
    __shared__ int cnt[4][NBINS];                // rank counters -> replica bases
    __shared__ int segoff[NBINS];
    __shared__ int gbase[NBINS];
    __shared__ int total[NBINS];
    int tid = threadIdx.x;
    int rep = (tid >> 5) & 3;                    // 16 warps -> 4 replicas
    for (int i = tid; i < 4 * NBINS; i += NTS) ((int*)cnt)[i] = 0;
    int base = blockIdx.x * NTS;                 // NTS int4 = 2048 edges
    int4 s = __ldcs(&src4[base + tid]);
    int4 d = __ldcs(&dst4[base + tid]);
    int ss[4] = {s.x, s.y, s.z, s.w};
    int dd[4] = {d.x, d.y, d.z, d.w};
    __syncthreads();
    unsigned wd[4]; int bn[4], rk[4];
#pragma unroll
    for (int r = 0; r < 4; r++) {
        bn[r] = dd[r] >> BSHIFT;
        wd[r] = ((unsigned)(dd[r] & (BINW - 1)) << 18) | (unsigned)ss[r];
        rk[r] = atomicAdd(&cnt[rep][bn[r]], 1);
    }
    __syncthreads();
    if (tid < NBINS) {                           // parallel replica merge
        int c0 = cnt[0][tid], c1 = cnt[1][tid], c2 = cnt[2][tid], c3 = cnt[3][tid];
        cnt[0][tid] = 0;
        cnt[1][tid] = c0;
        cnt[2][tid] = c0 + c1;
        cnt[3][tid] = c0 + c1 + c2;
        total[tid]  = c0 + c1 + c2 + c3;
    }
    __syncthreads();
    if (tid == 0) {                              // 98-entry serial bin scan
        int run = 0;
#pragma unroll 1
        for (int b = 0; b < NBINS; b++) { segoff[b] = run; run += total[b]; }
    }
    __syncthreads();
    if (tid < NBINS) gbase[tid] = atomicAdd(&d_cur[tid], total[tid]);
#pragma unroll
    for (int r = 0; r < 4; r++) {
        int p = segoff[bn[r]] + cnt[rep][bn[r]] + rk[r];
        stage[p] = wd[r];
        binof[p] = (unsigned char)bn[r];
    }
    __syncthreads();
    for (int i = tid; i < TILE; i += NTS) {
        int b = binof[i];
        int pos = gbase[b] + (i - segoff[b]);
        if (pos < CAPB)                          // never triggers; OOB guard
            d_edges[b * CAPB + pos] = stage[i];
    }
}

// ---------------- chunk bounds (quad-aligned) ----------------

__device__ __forceinline__ void chunk_quads(int cnt, int ch,
                                            int& q_lo, int& q_hi,
                                            int& tail_lo, int& tail_hi) {
    long long lo = ((long long)cnt * ch / NCHUNK) & ~3LL;
    long long hi = (ch == NCHUNK - 1) ? (long long)cnt
                                      : (((long long)cnt * (ch + 1) / NCHUNK) & ~3LL);
    q_lo = (int)(lo >> 2);
    q_hi = (int)(hi >> 2);
    tail_lo = (ch == NCHUNK - 1) ? (cnt & ~3) : 0;
    tail_hi = (ch == NCHUNK - 1) ? cnt : 0;
}

// ---------------- binned degree (uint4 reads, 512 threads) ----------------

__global__ void k_deg() {
    __shared__ int acc[BINW];
    int tid = threadIdx.x;
    int bin = blockIdx.x / NCHUNK, ch = blockIdx.x % NCHUNK;
    for (int i = tid; i < BINW; i += NTP) acc[i] = 0;
    __syncthreads();
    int cnt = d_cur[bin];
    int q_lo, q_hi, t_lo, t_hi;
    chunk_quads(cnt, ch, q_lo, q_hi, t_lo, t_hi);
    const uint4* E4 = (const uint4*)d_edges;
    int b4 = bin * CAPB4;
    for (int q = q_lo + tid; q < q_hi; q += NTP) {
        uint4 w = __ldcs(&E4[b4 + q]);
        atomicAdd(&acc[w.x >> 18], 1);
        atomicAdd(&acc[w.y >> 18], 1);
        atomicAdd(&acc[w.z >> 18], 1);
        atomicAdd(&acc[w.w >> 18], 1);
    }
    for (int e = t_lo + tid; e < t_hi; e += NTP)
        atomicAdd(&acc[__ldcs(&d_edges[bin * CAPB + e]) >> 18], 1);
    __syncthreads();
    for (int ld = tid; ld < BINW; ld += NTP) {
        int v = acc[ld];
        if (v)
            asm volatile("red.global.add.u32 [%0], %1;"
                         :: "l"(&d_cnt[(bin << BSHIFT) + ld]), "r"(v) : "memory");
    }
}

// ---------------- dense node kernels ----------------

__global__ void k_nodeA(const float2* __restrict__ x) {
    int i = blockIdx.x * blockDim.x + threadIdx.x;
    if (i >= NN) return;
    float deg  = (float)d_cnt[i] + 1.0f;        // +1 self-loop
    d_cnt[i] = 0;                               // re-zero for next run
    float dinv = rsqrtf(deg);
    d_dinv[i] = dinv;
    float2 xv = x[i];
    d_g[i] = make_float2(xv.x * dinv, xv.y * dinv);
}

__global__ void k_nodeB(const float2* __restrict__ x,
                        const float*  __restrict__ W1,   // [2,16]
                        const float*  __restrict__ b1,   // [16]
                        const float*  __restrict__ W2) { // [16,2]
    int i = blockIdx.x * blockDim.x + threadIdx.x;
    if (i >= NN) return;
    float dinv = d_dinv[i];
    float idg  = dinv * dinv;
    float2 xv  = __ldg(&x[i]);
    float2 u   = d_u[i];
    float ax = fmaf(u.x, dinv, xv.x * idg);
    float ay = fmaf(u.y, dinv, xv.y * idg);
    float h20 = 0.f, h21 = 0.f;
#pragma unroll
    for (int f = 0; f < 16; f++) {
        float a = fmaf(ax, __ldg(&W1[f]), fmaf(ay, __ldg(&W1[16 + f]), __ldg(&b1[f])));
        a = fmaxf(a, 0.f);
        h20 = fmaf(a, __ldg(&W2[2 * f]),     h20);
        h21 = fmaf(a, __ldg(&W2[2 * f + 1]), h21);
    }
    d_h2[i] = make_float2(h20, h21);
    d_g[i]  = make_float2(h20 * dinv, h21 * dinv);
    d_u[i]  = make_float2(0.f, 0.f);            // re-zero for pass 2
}

__global__ void k_nodeC(const float* __restrict__ b2, float2* __restrict__ out) {
    int i = blockIdx.x * blockDim.x + threadIdx.x;
    if (i < NBINS) d_cur[i] = 0;                // re-zero cursors for next run
    if (i >= NN) return;
    float dinv = d_dinv[i];
    float idg  = dinv * dinv;
    float2 u  = d_u[i];
    float2 h2 = d_h2[i];
    d_u[i] = make_float2(0.f, 0.f);             // re-zero for next run's pass 1
    out[i] = make_float2(fmaf(u.x, dinv, fmaf(h2.x, idg, __ldg(&b2[0]))),
                         fmaf(u.y, dinv, fmaf(h2.y, idg, __ldg(&b2[1]))));
}

// ---------------- binned gather pass (uint4 reads, 512 threads) -----------

__global__ void k_pass() {
    __shared__ float accx[BINW];
    __shared__ float accy[BINW];
    int tid = threadIdx.x;
    int bin = blockIdx.x / NCHUNK, ch = blockIdx.x % NCHUNK;
    for (int i = tid; i < BINW; i += NTP) { accx[i] = 0.f; accy[i] = 0.f; }
    __syncthreads();
    int cnt = d_cur[bin];
    int q_lo, q_hi, t_lo, t_hi;
    chunk_quads(cnt, ch, q_lo, q_hi, t_lo, t_hi);
    const uint4* E4 = (const uint4*)d_edges;
    int b4 = bin * CAPB4;
    for (int q = q_lo + tid; q < q_hi; q += NTP) {
        uint4 w = __ldcs(&E4[b4 + q]);
        float2 g0 = __ldg(&d_g[w.x & 0x3FFFFu]);
        float2 g1 = __ldg(&d_g[w.y & 0x3FFFFu]);
        float2 g2 = __ldg(&d_g[w.z & 0x3FFFFu]);
        float2 g3 = __ldg(&d_g[w.w & 0x3FFFFu]);
        atomicAdd(&accx[w.x >> 18], g0.x); atomicAdd(&accy[w.x >> 18], g0.y);
        atomicAdd(&accx[w.y >> 18], g1.x); atomicAdd(&accy[w.y >> 18], g1.y);
        atomicAdd(&accx[w.z >> 18], g2.x); atomicAdd(&accy[w.z >> 18], g2.y);
        atomicAdd(&accx[w.w >> 18], g3.x); atomicAdd(&accy[w.w >> 18], g3.y);
    }
    for (int e = t_lo + tid; e < t_hi; e += NTP) {
        unsigned w = __ldcs(&d_edges[bin * CAPB + e]);
        float2 g = __ldg(&d_g[w & 0x3FFFFu]);
        atomicAdd(&accx[w >> 18], g.x);
        atomicAdd(&accy[w >> 18], g.y);
    }
    __syncthreads();
    for (int ld = tid; ld < BINW; ld += NTP) {
        float vx = accx[ld], vy = accy[ld];
        if (vx != 0.f || vy != 0.f)
            asm volatile("red.global.add.v2.f32 [%0], {%1, %2};"
                         :: "l"(&d_u[(bin << BSHIFT) + ld]), "f"(vx), "f"(vy)
                         : "memory");
    }
}

// ---------------- launch: 7 kernels ----------------

extern "C" void kernel_launch(void* const* d_in, const int* in_sizes, int n_in,
                              void* d_out, int out_size) {
    // metadata order: x, W1, b1, W2, b2, edge_index
    const float2* x  = (const float2*)d_in[0];
    const float*  W1 = (const float*) d_in[1];
    const float*  b1 = (const float*) d_in[2];
    const float*  W2 = (const float*) d_in[3];
    const float*  b2 = (const float*) d_in[4];
    const int*    ei = (const int*)   d_in[5];     // [2, NE] row-major
    const int4*   src4 = (const int4*)(ei);
    const int4*   dst4 = (const int4*)(ei + NE);
    float2* out = (float2*)d_out;

    const int NT = 256;
    const int nodeBlocks = (NN + NT - 1) / NT;
    const int dpBlocks   = NBINS * NCHUNK;          // 588

    // d_cur/d_cnt/d_u are zero on entry (module-load init + per-run re-zero).
    k_scatter<<<NTILES,     NTS>>>(src4, dst4);     // #1
    k_deg    <<<dpBlocks,   NTP>>>();               // #2
    k_nodeA  <<<nodeBlocks, NT>>>(x);               // #3
    k_pass   <<<dpBlocks,   NTP>>>();               // #4 -> ncu capture slot
    k_nodeB  <<<nodeBlocks, NT>>>(x, W1, b1, W2);   // #5
    k_pass   <<<dpBlocks,   NTP>>>();               // #6
    k_nodeC  <<<nodeBlocks, NT>>>(b2, out);         // #7
}

// round 17
// speedup vs baseline: 1.1128x; 1.1128x over previous
#include <cuda_runtime.h>

// GCN 2-layer, GB300 — round 17: consolidation on the R14 base (224.0us).
// Pass is AT its L1TEX-additive floor (49us gathers + 18us ATOMS + 7us
// reads/flush = 74us measured). Remaining visible slack: k_scatter's serial
// 98-entry tid0 scan (~3-4k dependent-LDS cyc/tile on the critical path)
// -> replaced with a warp-parallel shfl scan. Scatter shape reverted to the
// proven 256thr/8-edge/2-replica form. Edge reads __ldg (51MB fits L2 ->
// reuse across deg/pass1/pass2).

#define NN     200000
#define NE     12800000
#define BSHIFT 11
#define BINW   2048
#define NBINS  98                    // ceil(NN / BINW)
#define NPAD   (NBINS * BINW)        // 200704
#define TILE   2048
#define NTILES (NE / TILE)           // 6250
#define CAPB   140000                // per-bin capacity; CAPB%4==0
#define CAPB4  (CAPB / 4)
#define NCHUNK 6                     // 98*6=588 blocks
#define NTP    512                   // threads for deg/pass blocks

__device__ unsigned d_edges[NBINS * CAPB];  // packed (localdst<<18)|src
__device__ int      d_cur[NBINS];           // per-bin cursors (zeroed by nodeC)
__device__ int      d_cnt[NPAD];            // degrees     (zeroed by nodeA)
__device__ float2   d_u  [NPAD];            // accumulators (zeroed by nodeB/C)
__device__ float    d_dinv[NN];
__device__ float2   d_g  [NN];
__device__ float2   d_h2 [NN];

// ---------------- partition: tile-staged, warp-parallel scan --------------

__global__ void k_scatter(const int4* __restrict__ src4,
                          const int4* __restrict__ dst4) {
    __shared__ unsigned stage[TILE];             // 8 KB
    __shared__ unsigned char binof[TILE];        // 2 KB
    __shared__ int cnt[2][NBINS];                // replicated rank counters
    __shared__ int segoff[NBINS];
    __shared__ int base1[NBINS];
    __shared__ int gbase[NBINS];
    __shared__ int total[NBINS];
    int tid = threadIdx.x;
    int rep = (tid >> 5) & 1;
    for (int i = tid; i < 2 * NBINS; i += 256) ((int*)cnt)[i] = 0;
    int b4 = blockIdx.x * (TILE / 4);
    int4 sa = __ldcs(&src4[b4 + tid]);
    int4 sb = __ldcs(&src4[b4 + 256 + tid]);
    int4 da = __ldcs(&dst4[b4 + tid]);
    int4 db = __ldcs(&dst4[b4 + 256 + tid]);
    int ss[8] = {sa.x, sa.y, sa.z, sa.w, sb.x, sb.y, sb.z, sb.w};
    int dd[8] = {da.x, da.y, da.z, da.w, db.x, db.y, db.z, db.w};
    __syncthreads();
    unsigned wd[8]; int bn[8], rk[8];
#pragma unroll
    for (int r = 0; r < 8; r++) {
        bn[r] = dd[r] >> BSHIFT;
        wd[r] = ((unsigned)(dd[r] & (BINW - 1)) << 18) | (unsigned)ss[r];
        rk[r] = atomicAdd(&cnt[rep][bn[r]], 1);
    }
    __syncthreads();
    if (tid < 32) {                              // warp-parallel exclusive scan
        int b0 = tid * 4;
        int c[4], t[4];
#pragma unroll
        for (int k = 0; k < 4; k++) {
            int b = b0 + k;
            int v0 = (b < NBINS) ? cnt[0][b] : 0;
            int v1 = (b < NBINS) ? cnt[1][b] : 0;
            c[k] = v0;
            t[k] = v0 + v1;
        }
        int lsum = t[0] + t[1] + t[2] + t[3];
        int pre = lsum;
#pragma unroll
        for (int o = 1; o < 32; o <<= 1) {
            int v = __shfl_up_sync(0xffffffffu, pre, o);
            if (tid >= o) pre += v;
        }
        pre -= lsum;                             // exclusive prefix of lane sums
        int run = pre;
#pragma unroll
        for (int k = 0; k < 4; k++) {
            int b = b0 + k;
            if (b < NBINS) {
                segoff[b] = run;
                base1[b]  = run + c[k];
                total[b]  = t[k];
                run += t[k];
            }
        }
    }
    __syncthreads();
    if (tid < NBINS) gbase[tid] = atomicAdd(&d_cur[tid], total[tid]);
#pragma unroll
    for (int r = 0; r < 8; r++) {
        int p = (rep ? base1[bn[r]] : segoff[bn[r]]) + rk[r];
        stage[p] = wd[r];
        binof[p] = (unsigned char)bn[r];
    }
    __syncthreads();
    for (int i = tid; i < TILE; i += 256) {
        int b = binof[i];
        int pos = gbase[b] + (i - segoff[b]);
        if (pos < CAPB)                          // never triggers; OOB guard
            d_edges[b * CAPB + pos] = stage[i];
    }
}

// ---------------- chunk bounds (quad-aligned) ----------------

__device__ __forceinline__ void chunk_quads(int cnt, int ch,
                                            int& q_lo, int& q_hi,
                                            int& tail_lo, int& tail_hi) {
    long long lo = ((long long)cnt * ch / NCHUNK) & ~3LL;
    long long hi = (ch == NCHUNK - 1) ? (long long)cnt
                                      : (((long long)cnt * (ch + 1) / NCHUNK) & ~3LL);
    q_lo = (int)(lo >> 2);
    q_hi = (int)(hi >> 2);
    tail_lo = (ch == NCHUNK - 1) ? (cnt & ~3) : 0;
    tail_hi = (ch == NCHUNK - 1) ? cnt : 0;
}

// ---------------- binned degree (uint4 reads, 512 threads) ----------------

__global__ void k_deg() {
    __shared__ int acc[BINW];
    int tid = threadIdx.x;
    int bin = blockIdx.x / NCHUNK, ch = blockIdx.x % NCHUNK;
    for (int i = tid; i < BINW; i += NTP) acc[i] = 0;
    __syncthreads();
    int cnt = d_cur[bin];
    int q_lo, q_hi, t_lo, t_hi;
    chunk_quads(cnt, ch, q_lo, q_hi, t_lo, t_hi);
    const uint4* E4 = (const uint4*)d_edges;
    int b4 = bin * CAPB4;
    for (int q = q_lo + tid; q < q_hi; q += NTP) {
        uint4 w = __ldg(&E4[b4 + q]);            // default policy: L2 reuse
        atomicAdd(&acc[w.x >> 18], 1);
        atomicAdd(&acc[w.y >> 18], 1);
        atomicAdd(&acc[w.z >> 18], 1);
        atomicAdd(&acc[w.w >> 18], 1);
    }
    for (int e = t_lo + tid; e < t_hi; e += NTP)
        atomicAdd(&acc[__ldg(&d_edges[bin * CAPB + e]) >> 18], 1);
    __syncthreads();
    for (int ld = tid; ld < BINW; ld += NTP) {
        int v = acc[ld];
        if (v)
            asm volatile("red.global.add.u32 [%0], %1;"
                         :: "l"(&d_cnt[(bin << BSHIFT) + ld]), "r"(v) : "memory");
    }
}

// ---------------- dense node kernels ----------------

__global__ void k_nodeA(const float2* __restrict__ x) {
    int i = blockIdx.x * blockDim.x + threadIdx.x;
    if (i >= NN) return;
    float deg  = (float)d_cnt[i] + 1.0f;        // +1 self-loop
    d_cnt[i] = 0;                               // re-zero for next run
    float dinv = rsqrtf(deg);
    d_dinv[i] = dinv;
    float2 xv = x[i];
    d_g[i] = make_float2(xv.x * dinv, xv.y * dinv);
}

__global__ void k_nodeB(const float2* __restrict__ x,
                        const float*  __restrict__ W1,   // [2,16]
                        const float*  __restrict__ b1,   // [16]
                        const float*  __restrict__ W2) { // [16,2]
    int i = blockIdx.x * blockDim.x + threadIdx.x;
    if (i >= NN) return;
    float dinv = d_dinv[i];
    float idg  = dinv * dinv;
    float2 xv  = __ldg(&x[i]);
    float2 u   = d_u[i];
    float ax = fmaf(u.x, dinv, xv.x * idg);
    float ay = fmaf(u.y, dinv, xv.y * idg);
    float h20 = 0.f, h21 = 0.f;
#pragma unroll
    for (int f = 0; f < 16; f++) {
        float a = fmaf(ax, __ldg(&W1[f]), fmaf(ay, __ldg(&W1[16 + f]), __ldg(&b1[f])));
        a = fmaxf(a, 0.f);
        h20 = fmaf(a, __ldg(&W2[2 * f]),     h20);
        h21 = fmaf(a, __ldg(&W2[2 * f + 1]), h21);
    }
    d_h2[i] = make_float2(h20, h21);
    d_g[i]  = make_float2(h20 * dinv, h21 * dinv);
    d_u[i]  = make_float2(0.f, 0.f);            // re-zero for pass 2
}

__global__ void k_nodeC(const float* __restrict__ b2, float2* __restrict__ out) {
    int i = blockIdx.x * blockDim.x + threadIdx.x;
    if (i < NBINS) d_cur[i] = 0;                // re-zero cursors for next run
    if (i >= NN) return;
    float dinv = d_dinv[i];
    float idg  = dinv * dinv;
    float2 u  = d_u[i];
    float2 h2 = d_h2[i];
    d_u[i] = make_float2(0.f, 0.f);             // re-zero for next run's pass 1
    out[i] = make_float2(fmaf(u.x, dinv, fmaf(h2.x, idg, __ldg(&b2[0]))),
                         fmaf(u.y, dinv, fmaf(h2.y, idg, __ldg(&b2[1]))));
}

// ---------------- binned gather pass (uint4 reads, 512 threads) -----------

__global__ void k_pass() {
    __shared__ float accx[BINW];
    __shared__ float accy[BINW];
    int tid = threadIdx.x;
    int bin = blockIdx.x / NCHUNK, ch = blockIdx.x % NCHUNK;
    for (int i = tid; i < BINW; i += NTP) { accx[i] = 0.f; accy[i] = 0.f; }
    __syncthreads();
    int cnt = d_cur[bin];
    int q_lo, q_hi, t_lo, t_hi;
    chunk_quads(cnt, ch, q_lo, q_hi, t_lo, t_hi);
    const uint4* E4 = (const uint4*)d_edges;
    int b4 = bin * CAPB4;
    for (int q = q_lo + tid; q < q_hi; q += NTP) {
        uint4 w = __ldg(&E4[b4 + q]);            // default policy: L2 reuse
        float2 g0 = __ldg(&d_g[w.x & 0x3FFFFu]);
        float2 g1 = __ldg(&d_g[w.y & 0x3FFFFu]);
        float2 g2 = __ldg(&d_g[w.z & 0x3FFFFu]);
        float2 g3 = __ldg(&d_g[w.w & 0x3FFFFu]);
        atomicAdd(&accx[w.x >> 18], g0.x); atomicAdd(&accy[w.x >> 18], g0.y);
        atomicAdd(&accx[w.y >> 18], g1.x); atomicAdd(&accy[w.y >> 18], g1.y);
        atomicAdd(&accx[w.z >> 18], g2.x); atomicAdd(&accy[w.z >> 18], g2.y);
        atomicAdd(&accx[w.w >> 18], g3.x); atomicAdd(&accy[w.w >> 18], g3.y);
    }
    for (int e = t_lo + tid; e < t_hi; e += NTP) {
        unsigned w = __ldg(&d_edges[bin * CAPB + e]);
        float2 g = __ldg(&d_g[w & 0x3FFFFu]);
        atomicAdd(&accx[w >> 18], g.x);
        atomicAdd(&accy[w >> 18], g.y);
    }
    __syncthreads();
    for (int ld = tid; ld < BINW; ld += NTP) {
        float vx = accx[ld], vy = accy[ld];
        if (vx != 0.f || vy != 0.f)
            asm volatile("red.global.add.v2.f32 [%0], {%1, %2};"
                         :: "l"(&d_u[(bin << BSHIFT) + ld]), "f"(vx), "f"(vy)
                         : "memory");
    }
}

// ---------------- launch: 7 kernels, k_pass in the captured 4th slot ------

extern "C" void kernel_launch(void* const* d_in, const int* in_sizes, int n_in,
                              void* d_out, int out_size) {
    // metadata order: x, W1, b1, W2, b2, edge_index
    const float2* x  = (const float2*)d_in[0];
    const float*  W1 = (const float*) d_in[1];
    const float*  b1 = (const float*) d_in[2];
    const float*  W2 = (const float*) d_in[3];
    const float*  b2 = (const float*) d_in[4];
    const int*    ei = (const int*)   d_in[5];     // [2, NE] row-major
    const int4*   src4 = (const int4*)(ei);
    const int4*   dst4 = (const int4*)(ei + NE);
    float2* out = (float2*)d_out;

    const int NT = 256;
    const int nodeBlocks = (NN + NT - 1) / NT;
    const int dpBlocks   = NBINS * NCHUNK;          // 588

    // d_cur/d_cnt/d_u are zero on entry (module-load init + per-run re-zero).
    k_scatter<<<NTILES,     NT>>>(src4, dst4);      // #1
    k_deg    <<<dpBlocks,   NTP>>>();               // #2
    k_nodeA  <<<nodeBlocks, NT>>>(x);               // #3
    k_pass   <<<dpBlocks,   NTP>>>();               // #4 -> ncu capture slot
    k_nodeB  <<<nodeBlocks, NT>>>(x, W1, b1, W2);   // #5
    k_pass   <<<dpBlocks,   NTP>>>();               // #6
    k_nodeC  <<<nodeBlocks, NT>>>(b2, out);         // #7
}